// round 1
// baseline (speedup 1.0000x reference)
#include <cuda_runtime.h>
#include <math.h>
#include <stdint.h>

#define B_ROWS 1024
#define M_TOT  200000
#define D_INP  256
#define DIM    128
#define D_OUT  10
#define TILE_M 128
#define NTILES ((M_TOT + TILE_M - 1) / TILE_M)   /* 1563 */
#define M_PAD  (NTILES * TILE_M)                 /* 200064 */
#define MAX_CTAS 512

// ---------------- device scratch (static globals: no runtime allocation) ----
__device__ float g_hT  [DIM * B_ROWS];     // h transposed: [d][b]
__device__ float g_hn2 [B_ROWS];
__device__ float g_hcT [DIM * M_PAD];      // hc transposed: [d][m], padded
__device__ float g_hcn2[M_PAD];
__device__ float g_part[(size_t)MAX_CTAS * B_ROWS * D_OUT];

// ---------------- kernel 1: h = x @ W^T + b, hn2 ----------------------------
__global__ void k_h(const float* __restrict__ x, const float* __restrict__ W,
                    const float* __restrict__ be) {
    __shared__ float xs[D_INP];
    __shared__ float red[DIM];
    int b = blockIdx.x, t = threadIdx.x;          // 128 threads
    xs[t]       = x[(size_t)b * D_INP + t];
    xs[t + 128] = x[(size_t)b * D_INP + t + 128];
    __syncthreads();
    const float4* W4 = (const float4*)(W + (size_t)t * D_INP);
    float s = be[t];
#pragma unroll 8
    for (int k4 = 0; k4 < D_INP / 4; k4++) {
        float4 w = W4[k4];
        s += w.x * xs[k4 * 4 + 0] + w.y * xs[k4 * 4 + 1]
           + w.z * xs[k4 * 4 + 2] + w.w * xs[k4 * 4 + 3];
    }
    g_hT[(size_t)t * B_ROWS + b] = s;
    red[t] = s * s;
    __syncthreads();
    for (int off = 64; off > 0; off >>= 1) {
        if (t < off) red[t] += red[t + off];
        __syncthreads();
    }
    if (t == 0) g_hn2[b] = red[0];
}

// ---------------- kernel 2: hc = candidate_x @ W^T + b (tiled SGEMM) --------
// tile: 128 rows (m) x 128 cols (d), K = 256 in chunks of 32.
__global__ __launch_bounds__(256) void k_hc(const float* __restrict__ cx,
                                            const float* __restrict__ W,
                                            const float* __restrict__ be) {
    __shared__ float cxs[32 * 132];   // [k][m] transposed staging
    __shared__ float ws [32 * 132];   // [k][d] transposed staging
    int tile = blockIdx.x;
    int tid  = threadIdx.x;
    int tx = tid & 15;   // m group
    int ty = tid >> 4;   // d group
    float acc[8][8];
#pragma unroll
    for (int i = 0; i < 8; i++)
#pragma unroll
        for (int j = 0; j < 8; j++) acc[i][j] = 0.f;

    int m_base = tile * TILE_M;
    for (int k0 = 0; k0 < D_INP; k0 += 32) {
#pragma unroll
        for (int i = 0; i < 4; i++) {
            int idx = tid + i * 256;   // 0..1023
            int r   = idx >> 3;        // row index (m for cx, d for W), 0..127
            int kq  = idx & 7;         // which float4 along k-chunk
            int mg  = m_base + r;
            float4 v = make_float4(0.f, 0.f, 0.f, 0.f);
            if (mg < M_TOT)
                v = *(const float4*)(cx + (size_t)mg * D_INP + k0 + kq * 4);
            cxs[(kq * 4 + 0) * 132 + r] = v.x;
            cxs[(kq * 4 + 1) * 132 + r] = v.y;
            cxs[(kq * 4 + 2) * 132 + r] = v.z;
            cxs[(kq * 4 + 3) * 132 + r] = v.w;
            float4 w = *(const float4*)(W + (size_t)r * D_INP + k0 + kq * 4);
            ws [(kq * 4 + 0) * 132 + r] = w.x;
            ws [(kq * 4 + 1) * 132 + r] = w.y;
            ws [(kq * 4 + 2) * 132 + r] = w.z;
            ws [(kq * 4 + 3) * 132 + r] = w.w;
        }
        __syncthreads();
#pragma unroll 4
        for (int k = 0; k < 32; k++) {
            float4 a0 = *(const float4*)(cxs + k * 132 + tx * 4);
            float4 a1 = *(const float4*)(cxs + k * 132 + tx * 4 + 64);
            float4 b0 = *(const float4*)(ws  + k * 132 + ty * 4);
            float4 b1 = *(const float4*)(ws  + k * 132 + ty * 4 + 64);
            float av[8] = {a0.x, a0.y, a0.z, a0.w, a1.x, a1.y, a1.z, a1.w};
            float bv[8] = {b0.x, b0.y, b0.z, b0.w, b1.x, b1.y, b1.z, b1.w};
#pragma unroll
            for (int i = 0; i < 8; i++)
#pragma unroll
                for (int j = 0; j < 8; j++) acc[i][j] += av[i] * bv[j];
        }
        __syncthreads();
    }

    // epilogue: add bias, write g_hcT [d][m], compute hcn2
    float bias[8];
#pragma unroll
    for (int j = 0; j < 8; j++) bias[j] = be[ty * 4 + (j & 3) + (j >> 2) * 64];
    float psum[8];
#pragma unroll
    for (int i = 0; i < 8; i++) psum[i] = 0.f;
#pragma unroll
    for (int i = 0; i < 8; i++) {
        int m = m_base + tx * 4 + (i & 3) + (i >> 2) * 64;
#pragma unroll
        for (int j = 0; j < 8; j++) {
            int d = ty * 4 + (j & 3) + (j >> 2) * 64;
            float v = acc[i][j] + bias[j];
            psum[i] += v * v;
            g_hcT[(size_t)d * M_PAD + m] = v;
        }
    }
    __syncthreads();                  // reuse cxs as [16][128] reduce buffer
    float* red = cxs;
#pragma unroll
    for (int i = 0; i < 8; i++) {
        int mloc = tx * 4 + (i & 3) + (i >> 2) * 64;
        red[ty * 128 + mloc] = psum[i];
    }
    __syncthreads();
    if (tid < 128) {
        float s = 0.f;
        for (int g = 0; g < 16; g++) s += red[g * 128 + tid];
        g_hcn2[m_base + tid] = s;
    }
}

// ---------------- kernel 3: fused dist-GEMM + exp + class accumulation ------
#define SMEM_MAIN_BYTES ((128*128 + 128*128 + 64*132 + 1024*10 + 128 + 128) * 4 + 128)

__global__ __launch_bounds__(256) void k_main(const int* __restrict__ cy) {
    extern __shared__ char smem[];
    float* h_s    = (float*)smem;              // 128k x 128b  (64 KB)
    float* hc_s   = h_s   + 128 * 128;         // 128k x 128m  (64 KB)
    float* e_s    = hc_s  + 128 * 128;         // 64 x 132     (33 KB, reused as ls)
    float* s_s    = e_s   + 64 * 132;          // 1024 x 10    (40 KB)
    float* hn2_s  = s_s   + 1024 * 10;         // 128
    float* hcn2_s = hn2_s + 128;               // 128
    unsigned char* cls_s = (unsigned char*)(hcn2_s + 128);   // 128 bytes

    int tid = threadIdx.x;
    int tm = tid & 15, tb = tid >> 4;

    for (int i = tid; i < 1024 * 10; i += 256) s_s[i] = 0.f;

    const float4* hcT4 = (const float4*)g_hcT;   // [128][M_PAD/4]
    const float4* hT4  = (const float4*)g_hT;    // [128][256]
    float4* h4 = (float4*)h_s;
    float4* c4 = (float4*)hc_s;

    for (int tile = blockIdx.x; tile < NTILES; tile += gridDim.x) {
        __syncthreads();   // protect hc_s / cls_s reuse across tiles
#pragma unroll
        for (int i = 0; i < 16; i++) {
            int idx = tid + i * 256;             // 4096 float4
            int d = idx >> 5, m4 = idx & 31;
            c4[d * 32 + m4] = hcT4[(size_t)d * (M_PAD / 4) + tile * 32 + m4];
        }
        if (tid < 128) {
            int mg = tile * TILE_M + tid;
            hcn2_s[tid] = g_hcn2[mg];
            cls_s[tid] = (mg < M_TOT) ? (unsigned char)cy[mg] : (unsigned char)255;
        }
        __syncthreads();

        for (int ch = 0; ch < 8; ch++) {
#pragma unroll
            for (int i = 0; i < 16; i++) {
                int idx = tid + i * 256;
                int d = idx >> 5, b4 = idx & 31;
                h4[d * 32 + b4] = hT4[(size_t)d * (B_ROWS / 4) + ch * 32 + b4];
            }
            if (tid < 128) hn2_s[tid] = g_hn2[ch * 128 + tid];
            __syncthreads();

            float acc[8][8];
#pragma unroll
            for (int i = 0; i < 8; i++)
#pragma unroll
                for (int j = 0; j < 8; j++) acc[i][j] = 0.f;

#pragma unroll 4
            for (int k = 0; k < 128; k++) {
                float4 a0 = h4[k * 32 + tb], a1 = h4[k * 32 + tb + 16];
                float4 b0 = c4[k * 32 + tm], b1 = c4[k * 32 + tm + 16];
                float av[8] = {a0.x, a0.y, a0.z, a0.w, a1.x, a1.y, a1.z, a1.w};
                float bv[8] = {b0.x, b0.y, b0.z, b0.w, b1.x, b1.y, b1.z, b1.w};
#pragma unroll
                for (int i = 0; i < 8; i++)
#pragma unroll
                    for (int j = 0; j < 8; j++) acc[i][j] += av[i] * bv[j];
            }

            // dist + exp (overwrite acc with e)
            float hn[8], cn[8];
#pragma unroll
            for (int i = 0; i < 8; i++) hn[i] = hn2_s[tb * 4 + (i & 3) + (i >> 2) * 64];
#pragma unroll
            for (int j = 0; j < 8; j++) cn[j] = hcn2_s[tm * 4 + (j & 3) + (j >> 2) * 64];
#pragma unroll
            for (int i = 0; i < 8; i++)
#pragma unroll
                for (int j = 0; j < 8; j++) {
                    float sq = fmaxf(hn[i] + cn[j] - 2.f * acc[i][j], 0.f);
                    acc[i][j] = __expf(-sqrtf(sq));
                }

#pragma unroll 1
            for (int half = 0; half < 2; half++) {
                __syncthreads();
#pragma unroll
                for (int i2 = 0; i2 < 4; i2++) {
                    int i = half * 4 + i2;
                    int r = tb * 4 + i2;          // local row 0..63
                    *(float4*)(e_s + r * 132 + tm * 4) =
                        make_float4(acc[i][0], acc[i][1], acc[i][2], acc[i][3]);
                    *(float4*)(e_s + r * 132 + tm * 4 + 64) =
                        make_float4(acc[i][4], acc[i][5], acc[i][6], acc[i][7]);
                }
                __syncthreads();
                // class-bucketed accumulation: 4 threads per row, 32 m each
                int bl = tid >> 2, q = tid & 3;
                float l[10];
#pragma unroll
                for (int c = 0; c < 10; c++) l[c] = 0.f;
#pragma unroll
                for (int t8 = 0; t8 < 8; t8++) {
                    float4 ev = *(const float4*)(e_s + bl * 132 + q * 32 + t8 * 4);
                    uchar4 cvv = *(const uchar4*)(cls_s + q * 32 + t8 * 4);
#pragma unroll
                    for (int c = 0; c < 10; c++) {
                        l[c] += (cvv.x == c) ? ev.x : 0.f;
                        l[c] += (cvv.y == c) ? ev.y : 0.f;
                        l[c] += (cvv.z == c) ? ev.z : 0.f;
                        l[c] += (cvv.w == c) ? ev.w : 0.f;
                    }
                }
                __syncthreads();
                float* ls = e_s;                  // reuse e_s as [256][10]
#pragma unroll
                for (int c = 0; c < 10; c++) ls[tid * 10 + c] = l[c];
                __syncthreads();
                for (int cell = tid; cell < 640; cell += 256) {
                    int bb = cell / 10, c = cell - bb * 10;
                    float v = ls[(bb * 4 + 0) * 10 + c] + ls[(bb * 4 + 1) * 10 + c]
                            + ls[(bb * 4 + 2) * 10 + c] + ls[(bb * 4 + 3) * 10 + c];
                    s_s[(ch * 128 + half * 64 + bb) * 10 + c] += v;
                }
            }
            __syncthreads();
        }
    }
    __syncthreads();
    for (int i = tid; i < 1024 * 10; i += 256)
        g_part[(size_t)blockIdx.x * (B_ROWS * D_OUT) + i] = s_s[i];
}

// ---------------- kernel 4: merge partials, softmax normalize, log ----------
__global__ void k_final(float* __restrict__ out, int nctas) {
    int b = blockIdx.x, t = threadIdx.x;   // 32 threads
    __shared__ float sc[10];
    if (t < 10) {
        float s = 0.f;
        for (int p = 0; p < nctas; p++)
            s += g_part[(size_t)p * (B_ROWS * D_OUT) + b * 10 + t];
        sc[t] = s;
    }
    __syncthreads();
    if (t < 10) {
        float tot = 0.f;
#pragma unroll
        for (int c = 0; c < 10; c++) tot += sc[c];
        out[b * 10 + t] = logf(sc[t] / tot + 1e-7f);
    }
}

// ---------------- launch -----------------------------------------------------
extern "C" void kernel_launch(void* const* d_in, const int* in_sizes, int n_in,
                              void* d_out, int out_size) {
    const float* x  = (const float*)d_in[0];
    const float* cx = (const float*)d_in[2];
    const int*   cy = (const int*)d_in[3];
    const float* W  = (const float*)d_in[4];
    const float* be = (const float*)d_in[5];
    float* out = (float*)d_out;

    int dev = 0;
    cudaGetDevice(&dev);
    int nsm = 148;
    cudaDeviceGetAttribute(&nsm, cudaDevAttrMultiProcessorCount, dev);
    int nctas = nsm;
    if (nctas > MAX_CTAS) nctas = MAX_CTAS;
    if (nctas < 1) nctas = 148;

    cudaFuncSetAttribute(k_main, cudaFuncAttributeMaxDynamicSharedMemorySize,
                         SMEM_MAIN_BYTES);

    k_h<<<B_ROWS, 128>>>(x, W, be);
    k_hc<<<NTILES, 256>>>(cx, W, be);
    k_main<<<nctas, 256, SMEM_MAIN_BYTES>>>(cy);
    k_final<<<B_ROWS, 32>>>(out, nctas);
}